// round 16
// baseline (speedup 1.0000x reference)
#include <cuda_runtime.h>
#include <cuda_fp16.h>
#include <cstdint>

#define BMAX 16384
__device__ float g_xp[BMAX * 512];
__device__ float g_hs[BMAX * 128];
__device__ float g_c2wt[32 * 9 * 64];   // conv2 weights [ic][k][oc]
__device__ float g_d1wt[64 * 9 * 32];   // deconv1 conv-equiv weights [ic][k][oc]

// enc/dec activations
__device__ __forceinline__ float fsig(float x) { return __fdividef(1.0f, 1.0f + __expf(-x)); }
// LSTM activations: single-MUFU tanh.approx
__device__ __forceinline__ float ltanh(float x) {
    float y; asm("tanh.approx.f32 %0, %1;" : "=f"(y) : "f"(x)); return y;
}
__device__ __forceinline__ float lsig(float x) {
    return fmaf(0.5f, ltanh(0.5f * x), 0.5f);
}
__device__ __forceinline__ void fma2(unsigned long long& acc, unsigned long long a, unsigned long long b) {
    asm("fma.rn.f32x2 %0, %1, %2, %0;" : "+l"(acc) : "l"(a), "l"(b));
}
__device__ __forceinline__ unsigned long long pk2(float x) {
    unsigned long long r; asm("mov.b64 %0, {%1,%2};" : "=l"(r) : "f"(x), "f"(x)); return r;
}
__device__ __forceinline__ float2 upk2(unsigned long long v) {
    float2 r; asm("mov.b64 {%0,%1}, %2;" : "=f"(r.x), "=f"(r.y) : "l"(v)); return r;
}
__device__ __forceinline__ __half2 u2h2(unsigned u) {
    __half2 h; *reinterpret_cast<unsigned*>(&h) = u; return h;
}

// ================= weight prep =================
__global__ void prep_kernel(const float* __restrict__ c2w, const float* __restrict__ d1w) {
    int i = blockIdx.x * 256 + threadIdx.x;
    if (i < 18432) {
        int oc = i / 288, r = i % 288, ic = r / 9, k = r % 9;
        g_c2wt[(ic * 9 + k) * 64 + oc] = c2w[i];
        int ic2 = i / 288, r2 = i % 288, oc2 = r2 / 9, kk = r2 % 9;
        g_d1wt[(ic2 * 9 + (8 - kk)) * 32 + oc2] = d1w[i];
    }
}

// ================= encoder + input projection (unchanged) =================
__global__ void __launch_bounds__(128) enc_kernel(
    const float* __restrict__ img, const float* __restrict__ act,
    const float* __restrict__ c1w, const float* __restrict__ c1b,
    const float* __restrict__ c2b,
    const float* __restrict__ encw, const float* __restrict__ encb,
    const float* __restrict__ wih, const float* __restrict__ bih,
    const float* __restrict__ bhh, int B)
{
    __shared__ float s_img[4][76];
    __shared__ float s_x[4][136];
    __shared__ float s_h2[4][1600];
    __shared__ float s_wt[4608];

    int tid = threadIdx.x, lane = tid & 31, w = tid >> 5;
    int gi = blockIdx.x * 4 + w;
    bool valid = gi < B;
    float* s_h1 = s_wt + w * 800;

    if (valid) {
        for (int i = lane; i < 75; i += 32) s_img[w][i] = img[gi * 75 + i];
        if (lane < 8) s_x[w][128 + lane] = act[gi * 8 + lane];
    }
    __syncwarp();

    int pidx[9];
    {
        int y = (lane < 25) ? lane / 5 : 0, x = (lane < 25) ? lane % 5 : 0;
        #pragma unroll
        for (int ky = 0; ky < 3; ky++)
            #pragma unroll
            for (int kx = 0; kx < 3; kx++) {
                int yy = y + ky - 1, xx = x + kx - 1;
                pidx[ky*3+kx] = (yy >= 0 && yy < 5 && xx >= 0 && xx < 5) ? yy*5+xx : -1;
            }
    }

    if (lane < 25) {
        float p1[27];
        #pragma unroll
        for (int ic = 0; ic < 3; ic++)
            #pragma unroll
            for (int j = 0; j < 9; j++)
                p1[ic*9+j] = (pidx[j] >= 0) ? s_img[w][ic*25 + pidx[j]] : 0.f;
        #pragma unroll 4
        for (int oc = 0; oc < 32; oc++) {
            float a = __ldg(&c1b[oc]);
            #pragma unroll
            for (int k = 0; k < 27; k++) a += p1[k] * __ldg(&c1w[oc*27+k]);
            s_h1[oc*25+lane] = fmaxf(a, 0.f);
        }
    }
    __syncwarp();

    if (lane < 25) {
        unsigned long long acc2[32];
        #pragma unroll
        for (int q = 0; q < 32; q++) acc2[q] = 0ull;
        for (int ic = 0; ic < 32; ic++) {
            const float* hp = s_h1 + ic * 25;
            unsigned long long p2[9];
            #pragma unroll
            for (int j = 0; j < 9; j++)
                p2[j] = pk2((pidx[j] >= 0) ? hp[pidx[j]] : 0.f);
            const ulonglong2* wt = reinterpret_cast<const ulonglong2*>(&g_c2wt[ic * 576]);
            #pragma unroll
            for (int k = 0; k < 9; k++) {
                #pragma unroll
                for (int q = 0; q < 16; q++) {
                    ulonglong2 wv = __ldg(&wt[k*16 + q]);
                    fma2(acc2[q*2],   p2[k], wv.x);
                    fma2(acc2[q*2+1], p2[k], wv.y);
                }
            }
        }
        #pragma unroll
        for (int q = 0; q < 32; q++) {
            float2 v = upk2(acc2[q]);
            s_h2[w][(2*q)*25   + lane] = fmaxf(v.x + __ldg(&c2b[2*q]),   0.f);
            s_h2[w][(2*q+1)*25 + lane] = fmaxf(v.y + __ldg(&c2b[2*q+1]), 0.f);
        }
    }
    __syncthreads();

    for (int ot = 0; ot < 4; ot++) {
        float acc = 0.f;
        for (int kt = 0; kt < 13; kt++) {
            int k0 = kt * 128, klen = (kt == 12) ? 64 : 128;
            __syncthreads();
            for (int idx = tid; idx < 32 * klen; idx += 128) {
                int r = idx / klen, k = idx - r * klen;
                s_wt[r*132 + k] = encw[(ot*32 + r)*1600 + k0 + k];
            }
            __syncthreads();
            const float4* wt4 = reinterpret_cast<const float4*>(&s_wt[lane*132]);
            const float4* h4  = reinterpret_cast<const float4*>(&s_h2[w][k0]);
            int n4 = klen >> 2;
            #pragma unroll 8
            for (int q = 0; q < n4; q++) {
                float4 wv = wt4[q], hv = h4[q];
                acc += wv.x*hv.x + wv.y*hv.y + wv.z*hv.z + wv.w*hv.w;
            }
        }
        s_x[w][ot*32 + lane] = acc + __ldg(&encb[ot*32 + lane]);
    }

    for (int ot = 0; ot < 16; ot++) {
        __syncthreads();
        for (int idx = tid; idx < 32 * 136; idx += 128) {
            int r = idx / 136, k = idx - r * 136;
            s_wt[r*144 + k] = wih[(ot*32 + r)*136 + k];
        }
        __syncthreads();
        float acc = 0.f;
        const float4* wt4 = reinterpret_cast<const float4*>(&s_wt[lane*144]);
        const float4* xv4 = reinterpret_cast<const float4*>(&s_x[w][0]);
        #pragma unroll 17
        for (int q = 0; q < 34; q++) {
            float4 wv = wt4[q], xv = xv4[q];
            acc += wv.x*xv.x + wv.y*xv.y + wv.z*xv.z + wv.w*xv.w;
        }
        if (valid) {
            int o = ot*32 + lane;
            g_xp[gi*512 + o] = acc + __ldg(&bih[o]) + __ldg(&bhh[o]);
        }
    }
}

// ================= LSTM: warp-local gate gather, ONE barrier/step =================
// Warp w owns rows 8w..8w+7. Lane = gate*8 + j, row = 8w + j.
// Matvec unchanged (64 HFMA2 on register weights, h broadcast from ONE shared
// double-buffered s_h). Gate gather = 4 shfl (src lane g*8+j) — no s_act, no
// second barrier. Epilogue replicated across the 4 gate-lanes (bit-identical
// f32 math); gate-0 lanes publish h.
__global__ void __launch_bounds__(512) lstm_kernel(
    const float* __restrict__ whh, float* __restrict__ d_out, int B, int out_size)
{
    if (blockIdx.x != 0) return;

    __shared__ __align__(16) __half s_h[2][128];

    int tid = threadIdx.x;
    int w = tid >> 5, lane = tid & 31;
    int gate = lane >> 3, j = lane & 7;
    int row = w * 8 + j;

    // weights for gate-row gate*128 + row
    __half2 w2[64];
    {
        const float4* rw = reinterpret_cast<const float4*>(&whh[(gate * 128 + row) * 128]);
        #pragma unroll
        for (int jj = 0; jj < 32; jj++) {
            float4 v = __ldg(&rw[jj]);
            w2[2*jj]   = __floats2half2_rn(v.x, v.y);
            w2[2*jj+1] = __floats2half2_rn(v.z, v.w);
        }
    }
    if (tid < 128) s_h[0][tid] = __float2half_rn(0.f);

    int xsel = gate * 128 + row;
    float xp0 = __ldg(&g_xp[xsel]);
    float xp1 = (B > 1) ? __ldg(&g_xp[512 + xsel]) : 0.f;
    __syncthreads();

    float c = 0.f;   // replicated across the 4 gate-lanes of this row
    for (int t = 0; t < B; t++) {
        // ---- matvec on shared h buffer (broadcast reads) ----
        const uint4* sh4 = reinterpret_cast<const uint4*>(s_h[t & 1]);
        __half2 hacc[4];
        #pragma unroll
        for (int ch = 0; ch < 4; ch++) {
            unsigned hw[16];
            uint4 q0 = sh4[ch*4+0], q1 = sh4[ch*4+1], q2 = sh4[ch*4+2], q3 = sh4[ch*4+3];
            hw[0]=q0.x; hw[1]=q0.y; hw[2]=q0.z; hw[3]=q0.w;
            hw[4]=q1.x; hw[5]=q1.y; hw[6]=q1.z; hw[7]=q1.w;
            hw[8]=q2.x; hw[9]=q2.y; hw[10]=q2.z; hw[11]=q2.w;
            hw[12]=q3.x; hw[13]=q3.y; hw[14]=q3.z; hw[15]=q3.w;
            __half2 acc = __float2half2_rn(0.f);
            #pragma unroll
            for (int jj = 0; jj < 16; jj++)
                acc = __hfma2(w2[ch*16 + jj], u2h2(hw[jj]), acc);
            hacc[ch] = acc;
        }
        __half2 s01 = __hadd2(hacc[0], hacc[1]);
        __half2 s23 = __hadd2(hacc[2], hacc[3]);
        float2 fs = __half22float2(__hadd2(s01, s23));
        float pre = xp0 + fs.x + fs.y;

        xp0 = xp1;
        if (t + 2 < B) xp1 = __ldg(&g_xp[(t+2)*512 + xsel]);

        float a = (gate == 2) ? ltanh(pre) : lsig(pre);

        // ---- warp-local gather: act of gate g for this row is at lane g*8+j ----
        float gi = __shfl_sync(0xffffffffu, a, j);
        float gf = __shfl_sync(0xffffffffu, a, 8 + j);
        float gg = __shfl_sync(0xffffffffu, a, 16 + j);
        float go = __shfl_sync(0xffffffffu, a, 24 + j);

        // ---- replicated epilogue (identical in all 4 gate-lanes) ----
        c = fmaf(gf, c, gi * gg);
        float h = go * ltanh(c);
        if (gate == 0) {
            s_h[(t + 1) & 1][row] = __float2half_rn(h);
            g_hs[t*128 + row] = h;
            if (t == B - 1) {
                d_out[out_size - 256 + row] = h;
                d_out[out_size - 128 + row] = c;
            }
        }
        __syncthreads();   // h buffer ready for next matvec
    }
}

// ================= decoder (unchanged) =================
__global__ void __launch_bounds__(128) dec_kernel(
    const float* __restrict__ decw, const float* __restrict__ decb,
    const float* __restrict__ d1b,
    const float* __restrict__ d2w, const float* __restrict__ d2b,
    float* __restrict__ out, int B)
{
    __shared__ float s_hs[4][128];
    __shared__ float s_d[4][1600];
    __shared__ float s_wt[4224];
    __shared__ float s_w2f[864];

    int tid = threadIdx.x, lane = tid & 31, w = tid >> 5;
    int gi = blockIdx.x * 4 + w;
    bool valid = gi < B;

    for (int i = tid; i < 864; i += 128) {
        int ic = i / 27, rem = i % 27, oc = rem / 9, k = rem % 9;
        s_w2f[i] = d2w[(ic*3 + oc)*9 + (8 - k)];
    }
    if (valid)
        for (int i = lane; i < 128; i += 32) s_hs[w][i] = g_hs[gi*128 + i];

    for (int ot = 0; ot < 50; ot++) {
        __syncthreads();
        for (int idx = tid; idx < 4096; idx += 128) {
            int r = idx >> 7, k = idx & 127;
            s_wt[r*132 + k] = decw[(ot*32 + r)*128 + k];
        }
        __syncthreads();
        float acc = 0.f;
        const float4* wt4 = reinterpret_cast<const float4*>(&s_wt[lane*132]);
        const float4* h4  = reinterpret_cast<const float4*>(&s_hs[w][0]);
        #pragma unroll 8
        for (int q = 0; q < 32; q++) {
            float4 wv = wt4[q], hv = h4[q];
            acc += wv.x*hv.x + wv.y*hv.y + wv.z*hv.z + wv.w*hv.w;
        }
        s_d[w][ot*32 + lane] = acc + __ldg(&decb[ot*32 + lane]);
    }
    __syncthreads();

    float* s_h1 = s_wt + w * 800;
    int pidx[9];
    {
        int y = (lane < 25) ? lane / 5 : 0, x = (lane < 25) ? lane % 5 : 0;
        #pragma unroll
        for (int ky = 0; ky < 3; ky++)
            #pragma unroll
            for (int kx = 0; kx < 3; kx++) {
                int yy = y + ky - 1, xx = x + kx - 1;
                pidx[ky*3+kx] = (yy >= 0 && yy < 5 && xx >= 0 && xx < 5) ? yy*5+xx : -1;
            }
    }

    if (lane < 25) {
        unsigned long long acc2[16];
        #pragma unroll
        for (int q = 0; q < 16; q++) acc2[q] = 0ull;
        for (int ic = 0; ic < 64; ic++) {
            const float* dp = &s_d[w][ic * 25];
            unsigned long long p2[9];
            #pragma unroll
            for (int j = 0; j < 9; j++)
                p2[j] = pk2((pidx[j] >= 0) ? dp[pidx[j]] : 0.f);
            const ulonglong2* wt = reinterpret_cast<const ulonglong2*>(&g_d1wt[ic * 288]);
            #pragma unroll
            for (int k = 0; k < 9; k++) {
                #pragma unroll
                for (int q = 0; q < 8; q++) {
                    ulonglong2 wv = __ldg(&wt[k*8 + q]);
                    fma2(acc2[q*2],   p2[k], wv.x);
                    fma2(acc2[q*2+1], p2[k], wv.y);
                }
            }
        }
        #pragma unroll
        for (int q = 0; q < 16; q++) {
            float2 v = upk2(acc2[q]);
            s_h1[(2*q)*25   + lane] = fmaxf(v.x + __ldg(&d1b[2*q]),   0.f);
            s_h1[(2*q+1)*25 + lane] = fmaxf(v.y + __ldg(&d1b[2*q+1]), 0.f);
        }
    }
    __syncwarp();

    if (valid && lane < 25) {
        float acc[3] = {__ldg(&d2b[0]), __ldg(&d2b[1]), __ldg(&d2b[2])};
        for (int ic = 0; ic < 32; ic++) {
            float p[9];
            #pragma unroll
            for (int j = 0; j < 9; j++)
                p[j] = (pidx[j] >= 0) ? s_h1[ic*25 + pidx[j]] : 0.f;
            #pragma unroll
            for (int oc = 0; oc < 3; oc++) {
                float a = acc[oc];
                #pragma unroll
                for (int k = 0; k < 9; k++) a += p[k] * s_w2f[ic*27 + oc*9 + k];
                acc[oc] = a;
            }
        }
        #pragma unroll
        for (int oc = 0; oc < 3; oc++)
            out[gi*75 + oc*25 + lane] = fsig(acc[oc]);
    }
}

extern "C" void kernel_launch(void* const* d_in, const int* in_sizes, int n_in,
                              void* d_out, int out_size)
{
    const float* img   = (const float*)d_in[0];
    const float* act   = (const float*)d_in[1];
    const float* c1w   = (const float*)d_in[2];
    const float* c1b   = (const float*)d_in[3];
    const float* c2w   = (const float*)d_in[4];
    const float* c2b   = (const float*)d_in[5];
    const float* encw  = (const float*)d_in[6];
    const float* encb  = (const float*)d_in[7];
    const float* wih   = (const float*)d_in[8];
    const float* whh   = (const float*)d_in[9];
    const float* bih   = (const float*)d_in[10];
    const float* bhh   = (const float*)d_in[11];
    const float* decw  = (const float*)d_in[12];
    const float* decb  = (const float*)d_in[13];
    const float* d1w   = (const float*)d_in[14];
    const float* d1b   = (const float*)d_in[15];
    const float* d2w   = (const float*)d_in[16];
    const float* d2b   = (const float*)d_in[17];
    float* out = (float*)d_out;

    int B = in_sizes[0] / 75;
    int blocks = (B + 3) / 4;

    prep_kernel<<<72, 256>>>(c2w, d1w);
    enc_kernel<<<blocks, 128>>>(img, act, c1w, c1b, c2b, encw, encb, wih, bih, bhh, B);
    lstm_kernel<<<148, 512>>>(whh, out, B, out_size);
    dec_kernel<<<blocks, 128>>>(decw, decb, d1b, d2w, d2b, out, B);
}

// round 17
// speedup vs baseline: 1.1227x; 1.1227x over previous
#include <cuda_runtime.h>
#include <cuda_fp16.h>
#include <cstdint>

#define BMAX 16384
__device__ float g_xp[BMAX * 512];
__device__ float g_hs[BMAX * 128];
__device__ float g_c2wt[32 * 9 * 64];   // conv2 weights [ic][k][oc]
__device__ float g_d1wt[64 * 9 * 32];   // deconv1 conv-equiv weights [ic][k][oc]

// enc/dec activations
__device__ __forceinline__ float fsig(float x) { return __fdividef(1.0f, 1.0f + __expf(-x)); }
// LSTM activations: single-MUFU tanh.approx
__device__ __forceinline__ float ltanh(float x) {
    float y; asm("tanh.approx.f32 %0, %1;" : "=f"(y) : "f"(x)); return y;
}
__device__ __forceinline__ float lsig(float x) {
    return fmaf(0.5f, ltanh(0.5f * x), 0.5f);
}
__device__ __forceinline__ void fma2(unsigned long long& acc, unsigned long long a, unsigned long long b) {
    asm("fma.rn.f32x2 %0, %1, %2, %0;" : "+l"(acc) : "l"(a), "l"(b));
}
__device__ __forceinline__ unsigned long long pk2(float x) {
    unsigned long long r; asm("mov.b64 %0, {%1,%2};" : "=l"(r) : "f"(x), "f"(x)); return r;
}
__device__ __forceinline__ float2 upk2(unsigned long long v) {
    float2 r; asm("mov.b64 {%0,%1}, %2;" : "=f"(r.x), "=f"(r.y) : "l"(v)); return r;
}
__device__ __forceinline__ __half2 u2h2(unsigned u) {
    __half2 h; *reinterpret_cast<unsigned*>(&h) = u; return h;
}

// ================= weight prep =================
__global__ void prep_kernel(const float* __restrict__ c2w, const float* __restrict__ d1w) {
    int i = blockIdx.x * 256 + threadIdx.x;
    if (i < 18432) {
        int oc = i / 288, r = i % 288, ic = r / 9, k = r % 9;
        g_c2wt[(ic * 9 + k) * 64 + oc] = c2w[i];
        int ic2 = i / 288, r2 = i % 288, oc2 = r2 / 9, kk = r2 % 9;
        g_d1wt[(ic2 * 9 + (8 - kk)) * 32 + oc2] = d1w[i];
    }
}

// ================= encoder + input projection (unchanged) =================
__global__ void __launch_bounds__(128) enc_kernel(
    const float* __restrict__ img, const float* __restrict__ act,
    const float* __restrict__ c1w, const float* __restrict__ c1b,
    const float* __restrict__ c2b,
    const float* __restrict__ encw, const float* __restrict__ encb,
    const float* __restrict__ wih, const float* __restrict__ bih,
    const float* __restrict__ bhh, int B)
{
    __shared__ float s_img[4][76];
    __shared__ float s_x[4][136];
    __shared__ float s_h2[4][1600];
    __shared__ float s_wt[4608];

    int tid = threadIdx.x, lane = tid & 31, w = tid >> 5;
    int gi = blockIdx.x * 4 + w;
    bool valid = gi < B;
    float* s_h1 = s_wt + w * 800;

    if (valid) {
        for (int i = lane; i < 75; i += 32) s_img[w][i] = img[gi * 75 + i];
        if (lane < 8) s_x[w][128 + lane] = act[gi * 8 + lane];
    }
    __syncwarp();

    int pidx[9];
    {
        int y = (lane < 25) ? lane / 5 : 0, x = (lane < 25) ? lane % 5 : 0;
        #pragma unroll
        for (int ky = 0; ky < 3; ky++)
            #pragma unroll
            for (int kx = 0; kx < 3; kx++) {
                int yy = y + ky - 1, xx = x + kx - 1;
                pidx[ky*3+kx] = (yy >= 0 && yy < 5 && xx >= 0 && xx < 5) ? yy*5+xx : -1;
            }
    }

    if (lane < 25) {
        float p1[27];
        #pragma unroll
        for (int ic = 0; ic < 3; ic++)
            #pragma unroll
            for (int j = 0; j < 9; j++)
                p1[ic*9+j] = (pidx[j] >= 0) ? s_img[w][ic*25 + pidx[j]] : 0.f;
        #pragma unroll 4
        for (int oc = 0; oc < 32; oc++) {
            float a = __ldg(&c1b[oc]);
            #pragma unroll
            for (int k = 0; k < 27; k++) a += p1[k] * __ldg(&c1w[oc*27+k]);
            s_h1[oc*25+lane] = fmaxf(a, 0.f);
        }
    }
    __syncwarp();

    if (lane < 25) {
        unsigned long long acc2[32];
        #pragma unroll
        for (int q = 0; q < 32; q++) acc2[q] = 0ull;
        for (int ic = 0; ic < 32; ic++) {
            const float* hp = s_h1 + ic * 25;
            unsigned long long p2[9];
            #pragma unroll
            for (int j = 0; j < 9; j++)
                p2[j] = pk2((pidx[j] >= 0) ? hp[pidx[j]] : 0.f);
            const ulonglong2* wt = reinterpret_cast<const ulonglong2*>(&g_c2wt[ic * 576]);
            #pragma unroll
            for (int k = 0; k < 9; k++) {
                #pragma unroll
                for (int q = 0; q < 16; q++) {
                    ulonglong2 wv = __ldg(&wt[k*16 + q]);
                    fma2(acc2[q*2],   p2[k], wv.x);
                    fma2(acc2[q*2+1], p2[k], wv.y);
                }
            }
        }
        #pragma unroll
        for (int q = 0; q < 32; q++) {
            float2 v = upk2(acc2[q]);
            s_h2[w][(2*q)*25   + lane] = fmaxf(v.x + __ldg(&c2b[2*q]),   0.f);
            s_h2[w][(2*q+1)*25 + lane] = fmaxf(v.y + __ldg(&c2b[2*q+1]), 0.f);
        }
    }
    __syncthreads();

    for (int ot = 0; ot < 4; ot++) {
        float acc = 0.f;
        for (int kt = 0; kt < 13; kt++) {
            int k0 = kt * 128, klen = (kt == 12) ? 64 : 128;
            __syncthreads();
            for (int idx = tid; idx < 32 * klen; idx += 128) {
                int r = idx / klen, k = idx - r * klen;
                s_wt[r*132 + k] = encw[(ot*32 + r)*1600 + k0 + k];
            }
            __syncthreads();
            const float4* wt4 = reinterpret_cast<const float4*>(&s_wt[lane*132]);
            const float4* h4  = reinterpret_cast<const float4*>(&s_h2[w][k0]);
            int n4 = klen >> 2;
            #pragma unroll 8
            for (int q = 0; q < n4; q++) {
                float4 wv = wt4[q], hv = h4[q];
                acc += wv.x*hv.x + wv.y*hv.y + wv.z*hv.z + wv.w*hv.w;
            }
        }
        s_x[w][ot*32 + lane] = acc + __ldg(&encb[ot*32 + lane]);
    }

    for (int ot = 0; ot < 16; ot++) {
        __syncthreads();
        for (int idx = tid; idx < 32 * 136; idx += 128) {
            int r = idx / 136, k = idx - r * 136;
            s_wt[r*144 + k] = wih[(ot*32 + r)*136 + k];
        }
        __syncthreads();
        float acc = 0.f;
        const float4* wt4 = reinterpret_cast<const float4*>(&s_wt[lane*144]);
        const float4* xv4 = reinterpret_cast<const float4*>(&s_x[w][0]);
        #pragma unroll 17
        for (int q = 0; q < 34; q++) {
            float4 wv = wt4[q], xv = xv4[q];
            acc += wv.x*xv.x + wv.y*xv.y + wv.z*xv.z + wv.w*xv.w;
        }
        if (valid) {
            int o = ot*32 + lane;
            g_xp[gi*512 + o] = acc + __ldg(&bih[o]) + __ldg(&bhh[o]);
        }
    }
}

// ================= LSTM: 256 threads, 2 gates per thread =================
// pair = tid>>7 (warp-uniform): pair0 owns (i,g), pair1 owns (f,o) of row tid&127.
// h loaded ONCE per thread, reused for both gate dots (LDS issues halved).
// pair0 computes u = sig(i)*tanh(g) locally -> s_u; pair1 owns c, h.
// Per step: 2 global barriers (256 thr), 1 float exchanged per row.
__global__ void __launch_bounds__(256) lstm_kernel(
    const float* __restrict__ whh, float* __restrict__ d_out, int B, int out_size)
{
    if (blockIdx.x != 0) return;

    __shared__ __align__(16) __half s_h[2][128];
    __shared__ float s_u[2][128];

    int tid = threadIdx.x;
    int pair = tid >> 7;                 // 0:(i,g) 1:(f,o) — warp-uniform
    int row = tid & 127;
    int gA = pair;                       // 0:i 1:f
    int gB = pair + 2;                   // 2:g 3:o

    // weights for both gate-rows (128 regs)
    __half2 wa[64], wb[64];
    {
        const float4* ra = reinterpret_cast<const float4*>(&whh[(gA * 128 + row) * 128]);
        const float4* rb = reinterpret_cast<const float4*>(&whh[(gB * 128 + row) * 128]);
        #pragma unroll
        for (int j = 0; j < 32; j++) {
            float4 va = __ldg(&ra[j]);
            wa[2*j]   = __floats2half2_rn(va.x, va.y);
            wa[2*j+1] = __floats2half2_rn(va.z, va.w);
            float4 vb = __ldg(&rb[j]);
            wb[2*j]   = __floats2half2_rn(vb.x, vb.y);
            wb[2*j+1] = __floats2half2_rn(vb.z, vb.w);
        }
    }
    if (tid < 128) s_h[0][tid] = __float2half_rn(0.f);

    int xA = gA * 128 + row, xB = gB * 128 + row;
    float xa0 = __ldg(&g_xp[xA]), xb0 = __ldg(&g_xp[xB]);
    float xa1 = 0.f, xb1 = 0.f;
    if (B > 1) { xa1 = __ldg(&g_xp[512 + xA]); xb1 = __ldg(&g_xp[512 + xB]); }
    __syncthreads();

    float c = 0.f;   // live in pair1 threads
    for (int t = 0; t < B; t++) {
        // ---- load h once, dot with BOTH gate weight rows ----
        const uint4* sh4 = reinterpret_cast<const uint4*>(s_h[t & 1]);
        __half2 aacc[4], bacc[4];
        #pragma unroll
        for (int ch = 0; ch < 4; ch++) {
            unsigned hw[16];
            uint4 q0 = sh4[ch*4+0], q1 = sh4[ch*4+1], q2 = sh4[ch*4+2], q3 = sh4[ch*4+3];
            hw[0]=q0.x; hw[1]=q0.y; hw[2]=q0.z; hw[3]=q0.w;
            hw[4]=q1.x; hw[5]=q1.y; hw[6]=q1.z; hw[7]=q1.w;
            hw[8]=q2.x; hw[9]=q2.y; hw[10]=q2.z; hw[11]=q2.w;
            hw[12]=q3.x; hw[13]=q3.y; hw[14]=q3.z; hw[15]=q3.w;
            __half2 aa = __float2half2_rn(0.f), bb = aa;
            #pragma unroll
            for (int j = 0; j < 16; j++) {
                __half2 hv = u2h2(hw[j]);
                aa = __hfma2(wa[ch*16 + j], hv, aa);
                bb = __hfma2(wb[ch*16 + j], hv, bb);
            }
            aacc[ch] = aa; bacc[ch] = bb;
        }
        float2 fa = __half22float2(__hadd2(__hadd2(aacc[0], aacc[1]), __hadd2(aacc[2], aacc[3])));
        float2 fb = __half22float2(__hadd2(__hadd2(bacc[0], bacc[1]), __hadd2(bacc[2], bacc[3])));
        float preA = xa0 + fa.x + fa.y;
        float preB = xb0 + fb.x + fb.y;

        xa0 = xa1; xb0 = xb1;
        if (t + 2 < B) {
            xa1 = __ldg(&g_xp[(t+2)*512 + xA]);
            xb1 = __ldg(&g_xp[(t+2)*512 + xB]);
        }

        if (pair == 0) {
            float gi = lsig(preA);          // i
            float gg = ltanh(preB);         // g
            s_u[t & 1][row] = gi * gg;
        }
        __syncthreads();                    // u ready (and prior h reads done)
        if (pair == 1) {
            float gf = lsig(preA);          // f
            float go = lsig(preB);          // o
            c = fmaf(gf, c, s_u[t & 1][row]);
            float h = go * ltanh(c);
            s_h[(t + 1) & 1][row] = __float2half_rn(h);
            g_hs[t*128 + row] = h;
            if (t == B - 1) {
                d_out[out_size - 256 + row] = h;
                d_out[out_size - 128 + row] = c;
            }
        }
        __syncthreads();                    // h(t+1) ready
    }
}

// ================= decoder (unchanged) =================
__global__ void __launch_bounds__(128) dec_kernel(
    const float* __restrict__ decw, const float* __restrict__ decb,
    const float* __restrict__ d1b,
    const float* __restrict__ d2w, const float* __restrict__ d2b,
    float* __restrict__ out, int B)
{
    __shared__ float s_hs[4][128];
    __shared__ float s_d[4][1600];
    __shared__ float s_wt[4224];
    __shared__ float s_w2f[864];

    int tid = threadIdx.x, lane = tid & 31, w = tid >> 5;
    int gi = blockIdx.x * 4 + w;
    bool valid = gi < B;

    for (int i = tid; i < 864; i += 128) {
        int ic = i / 27, rem = i % 27, oc = rem / 9, k = rem % 9;
        s_w2f[i] = d2w[(ic*3 + oc)*9 + (8 - k)];
    }
    if (valid)
        for (int i = lane; i < 128; i += 32) s_hs[w][i] = g_hs[gi*128 + i];

    for (int ot = 0; ot < 50; ot++) {
        __syncthreads();
        for (int idx = tid; idx < 4096; idx += 128) {
            int r = idx >> 7, k = idx & 127;
            s_wt[r*132 + k] = decw[(ot*32 + r)*128 + k];
        }
        __syncthreads();
        float acc = 0.f;
        const float4* wt4 = reinterpret_cast<const float4*>(&s_wt[lane*132]);
        const float4* h4  = reinterpret_cast<const float4*>(&s_hs[w][0]);
        #pragma unroll 8
        for (int q = 0; q < 32; q++) {
            float4 wv = wt4[q], hv = h4[q];
            acc += wv.x*hv.x + wv.y*hv.y + wv.z*hv.z + wv.w*hv.w;
        }
        s_d[w][ot*32 + lane] = acc + __ldg(&decb[ot*32 + lane]);
    }
    __syncthreads();

    float* s_h1 = s_wt + w * 800;
    int pidx[9];
    {
        int y = (lane < 25) ? lane / 5 : 0, x = (lane < 25) ? lane % 5 : 0;
        #pragma unroll
        for (int ky = 0; ky < 3; ky++)
            #pragma unroll
            for (int kx = 0; kx < 3; kx++) {
                int yy = y + ky - 1, xx = x + kx - 1;
                pidx[ky*3+kx] = (yy >= 0 && yy < 5 && xx >= 0 && xx < 5) ? yy*5+xx : -1;
            }
    }

    if (lane < 25) {
        unsigned long long acc2[16];
        #pragma unroll
        for (int q = 0; q < 16; q++) acc2[q] = 0ull;
        for (int ic = 0; ic < 64; ic++) {
            const float* dp = &s_d[w][ic * 25];
            unsigned long long p2[9];
            #pragma unroll
            for (int j = 0; j < 9; j++)
                p2[j] = pk2((pidx[j] >= 0) ? dp[pidx[j]] : 0.f);
            const ulonglong2* wt = reinterpret_cast<const ulonglong2*>(&g_d1wt[ic * 288]);
            #pragma unroll
            for (int k = 0; k < 9; k++) {
                #pragma unroll
                for (int q = 0; q < 8; q++) {
                    ulonglong2 wv = __ldg(&wt[k*8 + q]);
                    fma2(acc2[q*2],   p2[k], wv.x);
                    fma2(acc2[q*2+1], p2[k], wv.y);
                }
            }
        }
        #pragma unroll
        for (int q = 0; q < 16; q++) {
            float2 v = upk2(acc2[q]);
            s_h1[(2*q)*25   + lane] = fmaxf(v.x + __ldg(&d1b[2*q]),   0.f);
            s_h1[(2*q+1)*25 + lane] = fmaxf(v.y + __ldg(&d1b[2*q+1]), 0.f);
        }
    }
    __syncwarp();

    if (valid && lane < 25) {
        float acc[3] = {__ldg(&d2b[0]), __ldg(&d2b[1]), __ldg(&d2b[2])};
        for (int ic = 0; ic < 32; ic++) {
            float p[9];
            #pragma unroll
            for (int j = 0; j < 9; j++)
                p[j] = (pidx[j] >= 0) ? s_h1[ic*25 + pidx[j]] : 0.f;
            #pragma unroll
            for (int oc = 0; oc < 3; oc++) {
                float a = acc[oc];
                #pragma unroll
                for (int k = 0; k < 9; k++) a += p[k] * s_w2f[ic*27 + oc*9 + k];
                acc[oc] = a;
            }
        }
        #pragma unroll
        for (int oc = 0; oc < 3; oc++)
            out[gi*75 + oc*25 + lane] = fsig(acc[oc]);
    }
}

extern "C" void kernel_launch(void* const* d_in, const int* in_sizes, int n_in,
                              void* d_out, int out_size)
{
    const float* img   = (const float*)d_in[0];
    const float* act   = (const float*)d_in[1];
    const float* c1w   = (const float*)d_in[2];
    const float* c1b   = (const float*)d_in[3];
    const float* c2w   = (const float*)d_in[4];
    const float* c2b   = (const float*)d_in[5];
    const float* encw  = (const float*)d_in[6];
    const float* encb  = (const float*)d_in[7];
    const float* wih   = (const float*)d_in[8];
    const float* whh   = (const float*)d_in[9];
    const float* bih   = (const float*)d_in[10];
    const float* bhh   = (const float*)d_in[11];
    const float* decw  = (const float*)d_in[12];
    const float* decb  = (const float*)d_in[13];
    const float* d1w   = (const float*)d_in[14];
    const float* d1b   = (const float*)d_in[15];
    const float* d2w   = (const float*)d_in[16];
    const float* d2b   = (const float*)d_in[17];
    float* out = (float*)d_out;

    int B = in_sizes[0] / 75;
    int blocks = (B + 3) / 4;

    prep_kernel<<<72, 256>>>(c2w, d1w);
    enc_kernel<<<blocks, 128>>>(img, act, c1w, c1b, c2b, encw, encb, wih, bih, bhh, B);
    lstm_kernel<<<148, 256>>>(whh, out, B, out_size);
    dec_kernel<<<blocks, 128>>>(decw, decb, d1b, d2w, d2b, out, B);
}